// round 2
// baseline (speedup 1.0000x reference)
#include <cuda_runtime.h>
#include <cstdint>
#include <cstddef>

// Problem constants
#define BSZ   32
#define TT    512
#define INS   512
#define HH    512
#define G4    2048      // 4*H
#define NCTA  128       // persistent CTAs for recurrence
#define NTHR  256

// Scratch (static device memory: allocation-free rule)
__device__ float g_xg[(size_t)TT * BSZ * G4];   // [T][B][4H]  (134 MB)
__device__ float g_h[2][HH * BSZ];              // double-buffered h, [H][B]
__device__ unsigned g_bar;                      // monotonic grid-barrier counter

// ---------- packed fp32x2 helpers (Blackwell FFMA2 path) ----------
__device__ __forceinline__ unsigned long long pack2(float lo, float hi) {
    unsigned long long r;
    asm("mov.b64 %0, {%1, %2};" : "=l"(r) : "f"(lo), "f"(hi));
    return r;
}
__device__ __forceinline__ void unpack2(unsigned long long v, float& lo, float& hi) {
    asm("mov.b64 {%0, %1}, %2;" : "=f"(lo), "=f"(hi) : "l"(v));
}
__device__ __forceinline__ void ffma2(unsigned long long& d,
                                      unsigned long long a,
                                      unsigned long long b) {
    asm("fma.rn.f32x2 %0, %1, %2, %0;" : "+l"(d) : "l"(a), "l"(b));
}

// =====================================================================
// Phase 1: xg[t][b][g] = sum_d x[b,t,d]*W_ih[g,d] + b_ih[g] + b_hh[g]
// M=16384 (b*512+t), N=2048, K=512.  BM=BN=128, BK=16, 8x8 microtile.
// =====================================================================
__global__ void __launch_bounds__(256) gemm_xg_kernel(
    const float* __restrict__ x,
    const float* __restrict__ Wih,
    const float* __restrict__ bih,
    const float* __restrict__ bhh)
{
    __shared__ float As[16][132];   // [k][m], padded
    __shared__ float Bs[16][132];   // [k][n], padded

    const int m0  = blockIdx.x * 128;
    const int n0  = blockIdx.y * 128;
    const int tid = threadIdx.x;
    const int tx  = tid & 15;       // n direction
    const int ty  = tid >> 4;       // m direction

    unsigned long long acc[8][4];
#pragma unroll
    for (int i = 0; i < 8; ++i)
#pragma unroll
        for (int p = 0; p < 4; ++p) acc[i][p] = 0ULL;

    for (int k0 = 0; k0 < 512; k0 += 16) {
#pragma unroll
        for (int s = 0; s < 2; ++s) {
            int idx = tid + s * 256;          // 0..511
            int row = idx >> 2;
            int cid = idx & 3;
            float4 va = *reinterpret_cast<const float4*>(
                &x[(size_t)(m0 + row) * 512 + k0 + cid * 4]);
            As[cid * 4 + 0][row] = va.x;
            As[cid * 4 + 1][row] = va.y;
            As[cid * 4 + 2][row] = va.z;
            As[cid * 4 + 3][row] = va.w;
            float4 vb = *reinterpret_cast<const float4*>(
                &Wih[(size_t)(n0 + row) * 512 + k0 + cid * 4]);
            Bs[cid * 4 + 0][row] = vb.x;
            Bs[cid * 4 + 1][row] = vb.y;
            Bs[cid * 4 + 2][row] = vb.z;
            Bs[cid * 4 + 3][row] = vb.w;
        }
        __syncthreads();
#pragma unroll
        for (int k = 0; k < 16; ++k) {
            float4 a0 = *reinterpret_cast<const float4*>(&As[k][ty * 8]);
            float4 a1 = *reinterpret_cast<const float4*>(&As[k][ty * 8 + 4]);
            ulonglong2 b0 = *reinterpret_cast<const ulonglong2*>(&Bs[k][tx * 8]);
            ulonglong2 b1 = *reinterpret_cast<const ulonglong2*>(&Bs[k][tx * 8 + 4]);
            unsigned long long aa[8];
            aa[0] = pack2(a0.x, a0.x); aa[1] = pack2(a0.y, a0.y);
            aa[2] = pack2(a0.z, a0.z); aa[3] = pack2(a0.w, a0.w);
            aa[4] = pack2(a1.x, a1.x); aa[5] = pack2(a1.y, a1.y);
            aa[6] = pack2(a1.z, a1.z); aa[7] = pack2(a1.w, a1.w);
#pragma unroll
            for (int i = 0; i < 8; ++i) {
                ffma2(acc[i][0], aa[i], b0.x);
                ffma2(acc[i][1], aa[i], b0.y);
                ffma2(acc[i][2], aa[i], b1.x);
                ffma2(acc[i][3], aa[i], b1.y);
            }
        }
        __syncthreads();
    }

    float bias[8];
#pragma unroll
    for (int j = 0; j < 8; ++j) {
        int n = n0 + tx * 8 + j;
        bias[j] = bih[n] + bhh[n];
    }
#pragma unroll
    for (int i = 0; i < 8; ++i) {
        int m = m0 + ty * 8 + i;
        int t = m & 511;
        int b = m >> 9;
        float o[8];
#pragma unroll
        for (int p = 0; p < 4; ++p) unpack2(acc[i][p], o[2 * p], o[2 * p + 1]);
#pragma unroll
        for (int j = 0; j < 8; ++j) o[j] += bias[j];
        float* dst = &g_xg[((size_t)t * 32 + b) * 2048 + n0 + tx * 8];
        *reinterpret_cast<float4*>(dst)     = make_float4(o[0], o[1], o[2], o[3]);
        *reinterpret_cast<float4*>(dst + 4) = make_float4(o[4], o[5], o[6], o[7]);
    }
}

// =====================================================================
// Phase 2: persistent recurrent kernel. 128 CTAs x 256 threads.
// CTA owns j = j0..j0+3 (16 gate rows). W slice resident in smem.
// Per step: load h (per-warp 64-d slice), split-K partials, reduce,
// gate math (c in registers), write h + ReLU(h) to out, grid barrier.
// =====================================================================
__global__ void __launch_bounds__(256, 1) lstm_rec_kernel(
    const float* __restrict__ Whh,
    float* __restrict__ out)
{
    extern __shared__ float sm[];
    float* Ws  = sm;                  // [512][16]  8192 f
    float* Hs  = sm + 8192;           // [512][32] 16384 f
    float* Red = sm + 24576;          // [8][512]   4096 f
    float* Ho  = sm + 28672;          // [4][32]     128 f

    const int tid  = threadIdx.x;
    const int w    = tid >> 5;
    const int lane = tid & 31;
    const int j0   = blockIdx.x * 4;

    // Preload W_hh slice: Ws[d][gl], gl = gate*4 + jj, g = gate*512 + j0 + jj
    for (int idx = tid; idx < 8192; idx += 256) {
        int gl = idx >> 9;
        int d  = idx & 511;
        int g  = (gl >> 2) * 512 + j0 + (gl & 3);
        Ws[d * 16 + gl] = Whh[(size_t)g * 512 + d];
    }
    __syncthreads();

    const int jj = w;          // valid for tid < 128
    const int b  = lane;
    float c = 0.f;

    for (int t = 0; t < 512; ++t) {
        // xg prefetch (in flight across the compute below)
        float xi = 0.f, xf = 0.f, xz = 0.f, xo = 0.f;
        if (tid < 128) {
            const float* xp = &g_xg[((size_t)t * 32 + b) * 2048 + j0 + jj];
            xi = xp[0]; xf = xp[512]; xz = xp[1024]; xo = xp[1536];
        }

        // h slice load (warp w owns d in [64w, 64w+64))
        {
            float4* Hd = reinterpret_cast<float4*>(Hs + w * 2048);
            if (t == 0) {
                float4 z = make_float4(0.f, 0.f, 0.f, 0.f);
                for (int i = lane; i < 512; i += 32) Hd[i] = z;
            } else {
                const float4* hsrc =
                    reinterpret_cast<const float4*>(&g_h[(t + 1) & 1][w * 2048]);
                for (int i = lane; i < 512; i += 32) Hd[i] = hsrc[i];
            }
        }
        __syncwarp();

        // split-K partials: 16 gate-rows x (b = lane), K-slice of 64
        unsigned long long acc[8];
#pragma unroll
        for (int p = 0; p < 8; ++p) acc[p] = 0ULL;
#pragma unroll 4
        for (int dd = 0; dd < 64; ++dd) {
            int d = w * 64 + dd;
            float hv = Hs[d * 32 + lane];
            unsigned long long hh = pack2(hv, hv);
            const ulonglong2* wrow =
                reinterpret_cast<const ulonglong2*>(&Ws[d * 16]);
            ulonglong2 w01 = wrow[0];
            ulonglong2 w23 = wrow[1];
            ulonglong2 w45 = wrow[2];
            ulonglong2 w67 = wrow[3];
            ffma2(acc[0], hh, w01.x); ffma2(acc[1], hh, w01.y);
            ffma2(acc[2], hh, w23.x); ffma2(acc[3], hh, w23.y);
            ffma2(acc[4], hh, w45.x); ffma2(acc[5], hh, w45.y);
            ffma2(acc[6], hh, w67.x); ffma2(acc[7], hh, w67.y);
        }
#pragma unroll
        for (int p = 0; p < 8; ++p) {
            float f0, f1;
            unpack2(acc[p], f0, f1);
            Red[w * 512 + (2 * p)     * 32 + lane] = f0;
            Red[w * 512 + (2 * p + 1) * 32 + lane] = f1;
        }
        __syncthreads();

        if (tid < 128) {
            float s0 = 0.f, s1 = 0.f, s2 = 0.f, s3 = 0.f;
#pragma unroll
            for (int ww = 0; ww < 8; ++ww) {
                int base = ww * 512 + jj * 32 + b;
                s0 += Red[base];
                s1 += Red[base + 128];
                s2 += Red[base + 256];
                s3 += Red[base + 384];
            }
            float ig = 1.f / (1.f + __expf(-(xi + s0)));
            float fg = 1.f / (1.f + __expf(-(xf + s1)));
            float gg = tanhf(xz + s2);
            float og = 1.f / (1.f + __expf(-(xo + s3)));
            c = fg * c + ig * gg;
            float hval = og * tanhf(c);
            g_h[t & 1][(j0 + jj) * 32 + b] = hval;          // raw h feeds recurrence
            Ho[jj * 32 + b] = fmaxf(hval, 0.f);             // ReLU only on output
        }
        __syncthreads();

        if (tid < 32) {
            int bb = tid;
            float4 v = make_float4(Ho[bb], Ho[32 + bb], Ho[64 + bb], Ho[96 + bb]);
            *reinterpret_cast<float4*>(&out[((size_t)bb * 512 + t) * 512 + j0]) = v;
        }

        // ---- grid barrier (monotonic counter; valid across graph replays) ----
        __syncthreads();
        if (tid == 0) {
            __threadfence();
            unsigned ticket = atomicAdd(&g_bar, 1u);
            unsigned target = (ticket / (unsigned)NCTA + 1u) * (unsigned)NCTA;
            while (*((volatile unsigned*)&g_bar) < target) { }
            __threadfence();
        }
        __syncthreads();
    }
}

extern "C" void kernel_launch(void* const* d_in, const int* in_sizes, int n_in,
                              void* d_out, int out_size)
{
    const float* x   = (const float*)d_in[0];
    const float* Wih = (const float*)d_in[1];
    const float* Whh = (const float*)d_in[2];
    const float* bih = (const float*)d_in[3];
    const float* bhh = (const float*)d_in[4];
    float* out = (float*)d_out;

    dim3 g1(128, 16);
    gemm_xg_kernel<<<g1, 256>>>(x, Wih, bih, bhh);

    const int smem = 28800 * (int)sizeof(float);  // 115200 B
    cudaFuncSetAttribute(lstm_rec_kernel,
                         cudaFuncAttributeMaxDynamicSharedMemorySize, smem);
    lstm_rec_kernel<<<NCTA, NTHR, smem>>>(Whh, out);
}